// round 1
// baseline (speedup 1.0000x reference)
#include <cuda_runtime.h>

#define Bx 32
#define Tt 36
#define Nn 10000
#define Ff 3
#define Hh 10
#define Rr 20

// Scratch (no device allocation allowed -> __device__ globals)
__device__ float  g_tm[Bx * Nn];     // time_mean[b,n]
__device__ int    g_cl[Nn];          // decoded cluster ids
__device__ float  g_reg[Bx * Rr];    // regional[b,r] (NaN if empty region)
__device__ double g_gs[Bx];          // per-b sum of valid time_mean
__device__ int    g_gc[Bx];          // per-b count of valid time_mean
__device__ float  g_g1;              // global nanmean of pred_speed

// ---------------------------------------------------------------------------
// Kernel 0: decode cluster_id. The reference declares int64 but JAX may have
// silently produced int32 (x64 disabled). Detect at runtime: if the buffer is
// little-endian int64 with values in [0,20), every odd 32-bit word is 0 and
// every even word < 20. For genuine int32 data the probability that 64
// consecutive odd-index region ids are all zero is 20^-64 ~ 0.
// ---------------------------------------------------------------------------
__global__ void k_decode(const int* __restrict__ cl) {
    __shared__ int s64;
    if (threadIdx.x == 0) {
        int is64 = 1;
        for (int i = 0; i < 64; i++) {
            if (cl[2 * i + 1] != 0 || (unsigned)cl[2 * i] >= (unsigned)Rr) { is64 = 0; break; }
        }
        s64 = is64;
    }
    __syncthreads();
    int is64 = s64;
    for (int n = blockIdx.x * blockDim.x + threadIdx.x; n < Nn; n += gridDim.x * blockDim.x)
        g_cl[n] = is64 ? cl[2 * n] : cl[n];
}

// ---------------------------------------------------------------------------
// Kernel A (the heavy one, HBM-bound): time_mean[b,n] = nanmean_t seq[b,t,n,0]
// One thread per (b,n); 36 strided streaming loads, fully unrolled for MLP.
// ---------------------------------------------------------------------------
__global__ void k_tmean(const float* __restrict__ seq) {
    int idx = blockIdx.x * blockDim.x + threadIdx.x;
    if (idx >= Bx * Nn) return;
    int b = idx / Nn;
    int n = idx - b * Nn;
    const float* p = seq + ((size_t)(b * Tt) * Nn + n) * Ff;
    float s = 0.0f;
    int   c = 0;
#pragma unroll
    for (int t = 0; t < Tt; t++) {
        float v = __ldcs(p + (size_t)t * (Nn * Ff));
        bool ok = (v == v);
        s += ok ? v : 0.0f;
        c += ok ? 1 : 0;
    }
    g_tm[idx] = s / (float)c;   // 0/0 -> NaN, matching reference semantics
}

// ---------------------------------------------------------------------------
// Kernel B: one warp per (b, region). Scans the 40KB time_mean row (L2-hot),
// no atomics; warp-shfl reduction in double. r==0 warps also accumulate the
// per-b global sum/count for g1.
// ---------------------------------------------------------------------------
__global__ void k_region() {
    int gwid = (blockIdx.x * blockDim.x + threadIdx.x) >> 5;
    int lane = threadIdx.x & 31;
    if (gwid >= Bx * Rr) return;
    int b = gwid / Rr;
    int r = gwid - b * Rr;
    const float* tmrow = g_tm + b * Nn;
    double rs = 0.0; int rc = 0;
    double gs = 0.0; int gc = 0;
    for (int n = lane; n < Nn; n += 32) {
        float tm = tmrow[n];
        bool ok = (tm == tm);
        if (ok && g_cl[n] == r) { rs += (double)tm; rc++; }
        if (r == 0 && ok)       { gs += (double)tm; gc++; }
    }
#pragma unroll
    for (int o = 16; o; o >>= 1) {
        rs += __shfl_down_sync(0xffffffffu, rs, o);
        rc += __shfl_down_sync(0xffffffffu, rc, o);
        gs += __shfl_down_sync(0xffffffffu, gs, o);
        gc += __shfl_down_sync(0xffffffffu, gc, o);
    }
    if (lane == 0) {
        g_reg[b * Rr + r] = (float)(rs / (double)rc);  // 0/0 -> NaN
        if (r == 0) { g_gs[b] = gs; g_gc[b] = gc; }
    }
}

// ---------------------------------------------------------------------------
// Kernel C: single block. Finalize g1, compute g2 = nanmean(regional), write
// the B*H*R = 6400 regional outputs (NaN -> g2).
// ---------------------------------------------------------------------------
__global__ void k_final(float* __restrict__ out) {
    __shared__ double s_sum;
    __shared__ int    s_cnt;
    __shared__ float  s_g2;
    int tid = threadIdx.x;
    if (tid == 0) { s_sum = 0.0; s_cnt = 0; }
    __syncthreads();

    if (tid == 0) {
        double gs = 0.0; long long gc = 0;
        for (int b = 0; b < Bx; b++) { gs += g_gs[b]; gc += g_gc[b]; }
        g_g1 = (float)(gs / (double)gc);
    }

    double ls = 0.0; int lc = 0;
    for (int i = tid; i < Bx * Rr; i += blockDim.x) {
        float v = g_reg[i];
        if (v == v) { ls += (double)v; lc++; }
    }
    atomicAdd(&s_sum, ls);
    atomicAdd(&s_cnt, lc);
    __syncthreads();
    if (tid == 0) s_g2 = (float)(s_sum / (double)s_cnt);
    __syncthreads();

    float g2 = s_g2;
    float* oreg = out + (size_t)Bx * Hh * Nn;
    for (int i = tid; i < Bx * Hh * Rr; i += blockDim.x) {
        int b = i / (Hh * Rr);
        int r = i % Rr;
        float v = g_reg[b * Rr + r];
        oreg[i] = (v == v) ? v : g2;
    }
}

// ---------------------------------------------------------------------------
// Kernel D: out_pred[b,h,n] = time_mean[b,n] (NaN -> g1). One thread per
// (b,n), 10 coalesced stores.
// ---------------------------------------------------------------------------
__global__ void k_pred(float* __restrict__ out) {
    int idx = blockIdx.x * blockDim.x + threadIdx.x;
    if (idx >= Bx * Nn) return;
    int b = idx / Nn;
    int n = idx - b * Nn;
    float tm = g_tm[idx];
    float v = (tm == tm) ? tm : g_g1;
    float* o = out + (size_t)b * Hh * Nn + n;
#pragma unroll
    for (int h = 0; h < Hh; h++) o[(size_t)h * Nn] = v;
}

extern "C" void kernel_launch(void* const* d_in, const int* in_sizes, int n_in,
                              void* d_out, int out_size) {
    (void)in_sizes; (void)n_in; (void)out_size;
    const float* seq = (const float*)d_in[0];
    const int*   cl  = (const int*)d_in[1];
    float*       out = (float*)d_out;

    k_decode<<<40, 256>>>(cl);
    k_tmean<<<(Bx * Nn + 255) / 256, 256>>>(seq);
    k_region<<<(Bx * Rr * 32 + 255) / 256, 256>>>();
    k_final<<<1, 256>>>(out);
    k_pred<<<(Bx * Nn + 255) / 256, 256>>>(out);
}

// round 5
// speedup vs baseline: 1.4342x; 1.4342x over previous
#include <cuda_runtime.h>

#define Bx 32
#define Tt 36
#define Nn 10000
#define Ff 3
#define Hh 10
#define Rr 20

// Scratch (no device allocation allowed -> __device__ globals)
__device__ float  g_tm[Bx * Nn];     // time_mean[b,n]
__device__ int    g_cl[Nn];          // decoded cluster ids
__device__ float  g_reg[Bx * Rr];    // regional[b,r] (NaN if empty region)
__device__ double g_gs[Bx];          // per-b sum of valid time_mean
__device__ int    g_gc[Bx];          // per-b count of valid time_mean
__device__ float  g_g1;              // global nanmean of pred_speed

// ---------------------------------------------------------------------------
// Kernel 0 (single block): detect int64-vs-int32 serialization of cluster_id
// IN PARALLEL (64 threads, ballot via shared atomicAnd), then decode all
// 10000 ids. int64 little-endian with values in [0,20) => every odd 32-bit
// word is 0 and every even word < 20; probability of false positive for true
// int32 data is ~20^-64.
// ---------------------------------------------------------------------------
__global__ void k_decode(const int* __restrict__ cl) {
    __shared__ int s_flag;
    int tid = threadIdx.x;
    if (tid == 0) s_flag = 1;
    __syncthreads();
    if (tid < 64) {
        bool ok = (cl[2 * tid + 1] == 0) && ((unsigned)cl[2 * tid] < (unsigned)Rr);
        if (!ok) atomicAnd(&s_flag, 0);
    }
    __syncthreads();
    int is64 = s_flag;
    for (int n = tid; n < Nn; n += blockDim.x)
        g_cl[n] = is64 ? cl[2 * n] : cl[n];
}

// ---------------------------------------------------------------------------
// Kernel A (the heavy one, HBM-bound): time_mean[b,n] = nanmean_t seq[b,t,n,0]
// Vectorized: each thread handles 4 consecutive nodes via 3 float4 streaming
// loads per t (128B-aligned, fully coalesced). 36*3 = 108 LDG.128 per thread.
// ---------------------------------------------------------------------------
__global__ void k_tmean(const float4* __restrict__ seq) {
    int q = blockIdx.x * blockDim.x + threadIdx.x;
    const int NG = Nn / 4;                 // 2500 node-groups per b
    if (q >= Bx * NG) return;
    int b = q / NG;
    int j = q - b * NG;                    // node group index (nodes 4j..4j+3)
    const float4* p = seq + (size_t)b * Tt * (Nn * Ff / 4) + (size_t)j * 3;

    float s0 = 0.f, s1 = 0.f, s2 = 0.f, s3 = 0.f;
    int   c0 = 0,   c1 = 0,   c2 = 0,   c3 = 0;
#pragma unroll
    for (int t = 0; t < Tt; t++) {
        const float4* pt = p + (size_t)t * (Nn * Ff / 4);
        float4 va = __ldcs(pt);
        float4 vb = __ldcs(pt + 1);
        float4 vc = __ldcs(pt + 2);
        // floats f0..f11 cover nodes 4j..4j+3 (3 channels each); channel0 at
        // f0, f3, f6, f9 -> va.x, va.w, vb.z, vc.y
        float v0 = va.x, v1 = va.w, v2 = vb.z, v3 = vc.y;
        bool o0 = (v0 == v0), o1 = (v1 == v1), o2 = (v2 == v2), o3 = (v3 == v3);
        s0 += o0 ? v0 : 0.f;  c0 += o0;
        s1 += o1 ? v1 : 0.f;  c1 += o1;
        s2 += o2 ? v2 : 0.f;  c2 += o2;
        s3 += o3 ? v3 : 0.f;  c3 += o3;
    }
    int base = b * Nn + 4 * j;
    g_tm[base + 0] = s0 / (float)c0;   // 0/0 -> NaN, matching reference
    g_tm[base + 1] = s1 / (float)c1;
    g_tm[base + 2] = s2 / (float)c2;
    g_tm[base + 3] = s3 / (float)c3;
}

// ---------------------------------------------------------------------------
// Kernel B: one warp per (b, region). Scans the 40KB time_mean row (L2-hot),
// no atomics; warp-shfl reduction. r==0 warps also accumulate the per-b
// global sum/count for g1.
// ---------------------------------------------------------------------------
__global__ void k_region() {
    int gwid = (blockIdx.x * blockDim.x + threadIdx.x) >> 5;
    int lane = threadIdx.x & 31;
    if (gwid >= Bx * Rr) return;
    int b = gwid / Rr;
    int r = gwid - b * Rr;
    const float* tmrow = g_tm + b * Nn;
    double rs = 0.0; int rc = 0;
    double gs = 0.0; int gc = 0;
    for (int n = lane; n < Nn; n += 32) {
        float tm = tmrow[n];
        bool ok = (tm == tm);
        if (ok && g_cl[n] == r) { rs += (double)tm; rc++; }
        if (r == 0 && ok)       { gs += (double)tm; gc++; }
    }
#pragma unroll
    for (int o = 16; o; o >>= 1) {
        rs += __shfl_down_sync(0xffffffffu, rs, o);
        rc += __shfl_down_sync(0xffffffffu, rc, o);
        gs += __shfl_down_sync(0xffffffffu, gs, o);
        gc += __shfl_down_sync(0xffffffffu, gc, o);
    }
    if (lane == 0) {
        g_reg[b * Rr + r] = (float)(rs / (double)rc);  // 0/0 -> NaN
        if (r == 0) { g_gs[b] = gs; g_gc[b] = gc; }
    }
}

// ---------------------------------------------------------------------------
// Kernel C (single block, fully parallel): finalize g1 (warp 0, shfl over the
// 32 per-b partials), g2 = nanmean(regional) via block tree-reduce, then
// write the B*H*R = 6400 regional outputs (NaN -> g2).
// ---------------------------------------------------------------------------
__global__ void k_final(float* __restrict__ out) {
    __shared__ double s_ws[8];
    __shared__ int    s_wc[8];
    __shared__ float  s_g2;
    int tid  = threadIdx.x;
    int lane = tid & 31;
    int wid  = tid >> 5;

    // g1: Bx == 32 partials, one per lane of warp 0
    if (wid == 0) {
        double gs = g_gs[lane];
        int    gc = g_gc[lane];
#pragma unroll
        for (int o = 16; o; o >>= 1) {
            gs += __shfl_down_sync(0xffffffffu, gs, o);
            gc += __shfl_down_sync(0xffffffffu, gc, o);
        }
        if (lane == 0) g_g1 = (float)(gs / (double)gc);
    }

    // g2: reduce 640 regional values across the block
    double ls = 0.0; int lc = 0;
    for (int i = tid; i < Bx * Rr; i += blockDim.x) {
        float v = g_reg[i];
        if (v == v) { ls += (double)v; lc++; }
    }
#pragma unroll
    for (int o = 16; o; o >>= 1) {
        ls += __shfl_down_sync(0xffffffffu, ls, o);
        lc += __shfl_down_sync(0xffffffffu, lc, o);
    }
    if (lane == 0) { s_ws[wid] = ls; s_wc[wid] = lc; }
    __syncthreads();
    if (tid == 0) {
        double ts = 0.0; int tc = 0;
#pragma unroll
        for (int w = 0; w < 8; w++) { ts += s_ws[w]; tc += s_wc[w]; }
        s_g2 = (float)(ts / (double)tc);
    }
    __syncthreads();

    float g2 = s_g2;
    float* oreg = out + (size_t)Bx * Hh * Nn;
    for (int i = tid; i < Bx * Hh * Rr; i += blockDim.x) {
        int b = i / (Hh * Rr);
        int r = i % Rr;
        float v = g_reg[b * Rr + r];
        oreg[i] = (v == v) ? v : g2;
    }
}

// ---------------------------------------------------------------------------
// Kernel D: out_pred[b,h,n] = time_mean[b,n] (NaN -> g1). One thread per
// (b,n), 10 coalesced stores.
// ---------------------------------------------------------------------------
__global__ void k_pred(float* __restrict__ out) {
    int idx = blockIdx.x * blockDim.x + threadIdx.x;
    if (idx >= Bx * Nn) return;
    int b = idx / Nn;
    int n = idx - b * Nn;
    float tm = g_tm[idx];
    float v = (tm == tm) ? tm : g_g1;
    float* o = out + (size_t)b * Hh * Nn + n;
#pragma unroll
    for (int h = 0; h < Hh; h++) o[(size_t)h * Nn] = v;
}

extern "C" void kernel_launch(void* const* d_in, const int* in_sizes, int n_in,
                              void* d_out, int out_size) {
    (void)in_sizes; (void)n_in; (void)out_size;
    const float4* seq = (const float4*)d_in[0];
    const int*    cl  = (const int*)d_in[1];
    float*        out = (float*)d_out;

    k_decode<<<1, 256>>>(cl);
    k_tmean<<<(Bx * (Nn / 4) + 255) / 256, 256>>>(seq);
    k_region<<<(Bx * Rr * 32 + 255) / 256, 256>>>();
    k_final<<<1, 256>>>(out);
    k_pred<<<(Bx * Nn + 255) / 256, 256>>>(out);
}

// round 6
// speedup vs baseline: 2.3330x; 1.6267x over previous
#include <cuda_runtime.h>

#define Bx 32
#define Tt 36
#define Nn 10000
#define Ff 3
#define Hh 10
#define Rr 20
#define NQ (Nn * Ff / 4)   // 7500 float4 per (b,t) row

// Scratch (no device allocation allowed -> __device__ globals)
__device__ float  g_tm[Bx * Nn];     // time_mean[b,n]
__device__ float  g_reg[Bx * Rr];    // regional[b,r] (NaN if empty region)
__device__ double g_gs[Bx];          // per-b sum of valid time_mean
__device__ int    g_gc[Bx];          // per-b count of valid time_mean

// ---------------------------------------------------------------------------
// Kernel A (heavy, HBM-bound): time_mean[b,n] = nanmean_t seq[b,t,n,0]
// Thread <-> (b, j) with j a float4 column in [0, 7500). Each warp load is
// 32 consecutive float4 = 512B contiguous (4 lines/wavefront, minimal L1tex
// replays). Loop over T, unroll 4 for MLP without front-batching the queue.
// All 4 components are nansum'd uniformly (no divergence); only channel-0
// components (global float idx % 3 == 0) are written out.
// ---------------------------------------------------------------------------
__global__ void k_tmean(const float4* __restrict__ seq) {
    int idx = blockIdx.x * blockDim.x + threadIdx.x;
    if (idx >= Bx * NQ) return;
    int b = idx / NQ;
    int j = idx - b * NQ;
    const float4* p = seq + (size_t)b * Tt * NQ + j;

    float s0 = 0.f, s1 = 0.f, s2 = 0.f, s3 = 0.f;
    int   c0 = 0,   c1 = 0,   c2 = 0,   c3 = 0;
#pragma unroll 4
    for (int t = 0; t < Tt; t++) {
        float4 v = __ldcs(p + (size_t)t * NQ);
        bool o0 = (v.x == v.x), o1 = (v.y == v.y);
        bool o2 = (v.z == v.z), o3 = (v.w == v.w);
        s0 += o0 ? v.x : 0.f;  c0 += o0;
        s1 += o1 ? v.y : 0.f;  c1 += o1;
        s2 += o2 ? v.z : 0.f;  c2 += o2;
        s3 += o3 ? v.w : 0.f;  c3 += o3;
    }
    // global float index f = 4*j + c is channel 0 iff f % 3 == 0; node = f/3
    int f0 = 4 * j;
    float s[4] = {s0, s1, s2, s3};
    int   c[4] = {c0, c1, c2, c3};
#pragma unroll
    for (int cc = 0; cc < 4; cc++) {
        int f = f0 + cc;
        if (f % 3 == 0)
            g_tm[b * Nn + f / 3] = s[cc] / (float)c[cc];  // 0/0 -> NaN
    }
}

// ---------------------------------------------------------------------------
// Kernel B: one warp per (b, region). Per-block int64-vs-int32 detection of
// cluster_id serialization (int64 LE with values in [0,20) => odd words all
// zero; false-positive prob for true int32 ~ 20^-64), then warps scan the
// L2-hot time_mean row + cluster ids. r==0 warps also accumulate per-b
// global sum/count for g1.
// ---------------------------------------------------------------------------
__global__ void k_region(const int* __restrict__ cl) {
    __shared__ int s_flag;
    int tid = threadIdx.x;
    if (tid == 0) s_flag = 1;
    __syncthreads();
    if (tid < 64) {
        bool ok = (cl[2 * tid + 1] == 0) && ((unsigned)cl[2 * tid] < (unsigned)Rr);
        if (!ok) atomicAnd(&s_flag, 0);
    }
    __syncthreads();
    int is64 = s_flag;

    int gwid = (blockIdx.x * blockDim.x + tid) >> 5;
    int lane = tid & 31;
    if (gwid >= Bx * Rr) return;
    int b = gwid / Rr;
    int r = gwid - b * Rr;
    const float* tmrow = g_tm + b * Nn;
    double rs = 0.0; int rc = 0;
    double gs = 0.0; int gc = 0;
#pragma unroll 4
    for (int n = lane; n < Nn; n += 32) {
        float tm = tmrow[n];
        int   id = is64 ? cl[2 * n] : cl[n];
        bool ok = (tm == tm);
        if (ok && id == r) { rs += (double)tm; rc++; }
        if (r == 0 && ok)  { gs += (double)tm; gc++; }
    }
#pragma unroll
    for (int o = 16; o; o >>= 1) {
        rs += __shfl_down_sync(0xffffffffu, rs, o);
        rc += __shfl_down_sync(0xffffffffu, rc, o);
        gs += __shfl_down_sync(0xffffffffu, gs, o);
        gc += __shfl_down_sync(0xffffffffu, gc, o);
    }
    if (lane == 0) {
        g_reg[b * Rr + r] = (float)(rs / (double)rc);  // 0/0 -> NaN
        if (r == 0) { g_gs[b] = gs; g_gc[b] = gc; }
    }
}

// ---------------------------------------------------------------------------
// Kernel C (fused pred + final):
//  - every block re-derives g1 from the 32 per-b partials (warp 0, shfl)
//  - block 0 additionally computes g2 = nanmean(regional) and writes the
//    B*H*R = 6400 regional outputs (NaN -> g2)
//  - all blocks write out_pred[b,h,n] = time_mean[b,n] (NaN -> g1)
// ---------------------------------------------------------------------------
__global__ void k_predfinal(float* __restrict__ out) {
    __shared__ float s_g1;
    int tid  = threadIdx.x;
    int lane = tid & 31;

    if (tid < 32) {
        double gs = g_gs[lane];
        int    gc = g_gc[lane];
#pragma unroll
        for (int o = 16; o; o >>= 1) {
            gs += __shfl_down_sync(0xffffffffu, gs, o);
            gc += __shfl_down_sync(0xffffffffu, gc, o);
        }
        if (lane == 0) s_g1 = (float)(gs / (double)gc);
    }
    __syncthreads();
    float g1 = s_g1;

    if (blockIdx.x == 0) {
        __shared__ double s_ws[8];
        __shared__ int    s_wc[8];
        __shared__ float  s_g2;
        int wid = tid >> 5;
        double ls = 0.0; int lc = 0;
        for (int i = tid; i < Bx * Rr; i += blockDim.x) {
            float v = g_reg[i];
            if (v == v) { ls += (double)v; lc++; }
        }
#pragma unroll
        for (int o = 16; o; o >>= 1) {
            ls += __shfl_down_sync(0xffffffffu, ls, o);
            lc += __shfl_down_sync(0xffffffffu, lc, o);
        }
        if (lane == 0) { s_ws[wid] = ls; s_wc[wid] = lc; }
        __syncthreads();
        if (tid == 0) {
            double ts = 0.0; int tc = 0;
#pragma unroll
            for (int w = 0; w < 8; w++) { ts += s_ws[w]; tc += s_wc[w]; }
            s_g2 = (float)(ts / (double)tc);
        }
        __syncthreads();
        float g2 = s_g2;
        float* oreg = out + (size_t)Bx * Hh * Nn;
        for (int i = tid; i < Bx * Hh * Rr; i += blockDim.x) {
            int b = i / (Hh * Rr);
            int r = i % Rr;
            float v = g_reg[b * Rr + r];
            oreg[i] = (v == v) ? v : g2;
        }
    }

    // pred: one thread per (b,n), 10 coalesced stores
    int idx = blockIdx.x * blockDim.x + tid;
    if (idx >= Bx * Nn) return;
    int b = idx / Nn;
    int n = idx - b * Nn;
    float tm = g_tm[idx];
    float v = (tm == tm) ? tm : g1;
    float* o = out + (size_t)b * Hh * Nn + n;
#pragma unroll
    for (int h = 0; h < Hh; h++) o[(size_t)h * Nn] = v;
}

extern "C" void kernel_launch(void* const* d_in, const int* in_sizes, int n_in,
                              void* d_out, int out_size) {
    (void)in_sizes; (void)n_in; (void)out_size;
    const float4* seq = (const float4*)d_in[0];
    const int*    cl  = (const int*)d_in[1];
    float*        out = (float*)d_out;

    k_tmean<<<(Bx * NQ + 255) / 256, 256>>>(seq);
    k_region<<<(Bx * Rr * 32 + 255) / 256, 256>>>(cl);
    k_predfinal<<<(Bx * Nn + 255) / 256, 256>>>(out);
}

// round 7
// speedup vs baseline: 3.9413x; 1.6894x over previous
#include <cuda_runtime.h>

#define Bx 32
#define Tt 36
#define Nn 10000
#define Ff 3
#define Hh 10
#define Rr 20
#define NQ (Nn * Ff / 4)   // 7500 float4 per (b,t) row

// Scratch (no device allocation allowed -> __device__ globals)
__device__ float g_tm[Bx * Nn];      // time_mean[b,n]
__device__ float g_rsum[Bx * Rr];    // regional sum accumulators
__device__ int   g_rcnt[Bx * Rr];    // regional count accumulators
__device__ float g_gsum;             // global valid-tm sum (for g1)
__device__ int   g_gcnt;             // global valid-tm count

// ---------------------------------------------------------------------------
// Kernel Z: zero the atomic accumulators (graph replays reuse device globals).
// ---------------------------------------------------------------------------
__global__ void k_zero() {
    int tid = threadIdx.x;
    for (int i = tid; i < Bx * Rr; i += blockDim.x) { g_rsum[i] = 0.f; g_rcnt[i] = 0; }
    if (tid == 0) { g_gsum = 0.f; g_gcnt = 0; }
}

// ---------------------------------------------------------------------------
// Kernel A (heavy, HBM-bound, fused): grid = (30 chunks, 32 b), one block per
// (b, chunk-of-256-float4). Main loop: 36 coalesced float4 streaming loads per
// thread (512B/warp/load). Epilogue: write time_mean AND bin it into per-block
// shared region histograms (20 sums + 20 counts + global sum/count), flushed
// with ~44 global atomics per block. This replaces the old k_region scan
// (which redundantly re-read all nodes 20x with only 640 warps).
// cluster_id int64-vs-int32 detection done per block (odd 32-bit words all
// zero + even words < 20 => int64 LE; false-positive prob ~20^-64).
// ---------------------------------------------------------------------------
__global__ void k_tmean(const float4* __restrict__ seq, const int* __restrict__ cl) {
    __shared__ float s_rsum[Rr];
    __shared__ int   s_rcnt[Rr];
    __shared__ float s_gsum;
    __shared__ int   s_gcnt;
    __shared__ int   s_flag;

    int tid = threadIdx.x;
    int b   = blockIdx.y;
    int j   = blockIdx.x * blockDim.x + tid;   // float4 column in [0, NQ)

    if (tid < Rr) { s_rsum[tid] = 0.f; s_rcnt[tid] = 0; }
    if (tid == 0) { s_gsum = 0.f; s_gcnt = 0; s_flag = 1; }
    __syncthreads();
    if (tid < 64) {
        bool ok = (cl[2 * tid + 1] == 0) && ((unsigned)cl[2 * tid] < (unsigned)Rr);
        if (!ok) atomicAnd(&s_flag, 0);
    }

    float s0 = 0.f, s1 = 0.f, s2 = 0.f, s3 = 0.f;
    int   c0 = 0,   c1 = 0,   c2 = 0,   c3 = 0;
    if (j < NQ) {
        const float4* p = seq + (size_t)b * Tt * NQ + j;
#pragma unroll 4
        for (int t = 0; t < Tt; t++) {
            float4 v = p[(size_t)t * NQ];
            bool o0 = (v.x == v.x), o1 = (v.y == v.y);
            bool o2 = (v.z == v.z), o3 = (v.w == v.w);
            s0 += o0 ? v.x : 0.f;  c0 += o0;
            s1 += o1 ? v.y : 0.f;  c1 += o1;
            s2 += o2 ? v.z : 0.f;  c2 += o2;
            s3 += o3 ? v.w : 0.f;  c3 += o3;
        }
    }
    __syncthreads();   // s_flag ready; shared hist zeroed long ago
    int is64 = s_flag;

    if (j < NQ) {
        float s[4] = {s0, s1, s2, s3};
        int   c[4] = {c0, c1, c2, c3};
        int f0 = 4 * j;
#pragma unroll
        for (int cc = 0; cc < 4; cc++) {
            int f = f0 + cc;
            if (f % 3 == 0) {                      // channel-0 component
                int   node = f / 3;
                float tm = s[cc] / (float)c[cc];   // 0/0 -> NaN
                g_tm[b * Nn + node] = tm;
                if (tm == tm) {
                    int id = is64 ? cl[2 * node] : cl[node];
                    atomicAdd(&s_rsum[id], tm);
                    atomicAdd(&s_rcnt[id], 1);
                    atomicAdd(&s_gsum, tm);
                    atomicAdd(&s_gcnt, 1);
                }
            }
        }
    }
    __syncthreads();

    if (tid < Rr) {
        atomicAdd(&g_rsum[b * Rr + tid], s_rsum[tid]);
        atomicAdd(&g_rcnt[b * Rr + tid], s_rcnt[tid]);
    }
    if (tid == 0 && s_gcnt > 0) {
        atomicAdd(&g_gsum, s_gsum);
        atomicAdd(&g_gcnt, s_gcnt);
    }
}

// ---------------------------------------------------------------------------
// Kernel C (fused pred + final):
//  - every block reads g_gsum/g_gcnt -> g1
//  - block 0 finalizes regional[b,r] = rsum/rcnt (0/0 -> NaN), computes
//    g2 = nanmean(regional), writes the B*H*R = 6400 regional outputs
//  - all blocks write out_pred[b,h,n] = time_mean[b,n] (NaN -> g1)
// ---------------------------------------------------------------------------
__global__ void k_predfinal(float* __restrict__ out) {
    int tid  = threadIdx.x;
    float g1 = g_gsum / (float)g_gcnt;

    if (blockIdx.x == 0) {
        __shared__ double s_ws[8];
        __shared__ int    s_wc[8];
        __shared__ float  s_g2;
        __shared__ float  s_regv[Bx * Rr];
        int lane = tid & 31;
        int wid  = tid >> 5;
        double ls = 0.0; int lc = 0;
        for (int i = tid; i < Bx * Rr; i += blockDim.x) {
            float v = g_rsum[i] / (float)g_rcnt[i];   // 0/0 -> NaN
            s_regv[i] = v;
            if (v == v) { ls += (double)v; lc++; }
        }
#pragma unroll
        for (int o = 16; o; o >>= 1) {
            ls += __shfl_down_sync(0xffffffffu, ls, o);
            lc += __shfl_down_sync(0xffffffffu, lc, o);
        }
        if (lane == 0) { s_ws[wid] = ls; s_wc[wid] = lc; }
        __syncthreads();
        if (tid == 0) {
            double ts = 0.0; int tc = 0;
#pragma unroll
            for (int w = 0; w < 8; w++) { ts += s_ws[w]; tc += s_wc[w]; }
            s_g2 = (float)(ts / (double)tc);
        }
        __syncthreads();
        float g2 = s_g2;
        float* oreg = out + (size_t)Bx * Hh * Nn;
        for (int i = tid; i < Bx * Hh * Rr; i += blockDim.x) {
            int b = i / (Hh * Rr);
            int r = i % Rr;
            float v = s_regv[b * Rr + r];
            oreg[i] = (v == v) ? v : g2;
        }
    }

    // pred: one thread per (b,n), 10 coalesced stores
    int idx = blockIdx.x * blockDim.x + tid;
    if (idx >= Bx * Nn) return;
    int b = idx / Nn;
    int n = idx - b * Nn;
    float tm = g_tm[idx];
    float v = (tm == tm) ? tm : g1;
    float* o = out + (size_t)b * Hh * Nn + n;
#pragma unroll
    for (int h = 0; h < Hh; h++) o[(size_t)h * Nn] = v;
}

extern "C" void kernel_launch(void* const* d_in, const int* in_sizes, int n_in,
                              void* d_out, int out_size) {
    (void)in_sizes; (void)n_in; (void)out_size;
    const float4* seq = (const float4*)d_in[0];
    const int*    cl  = (const int*)d_in[1];
    float*        out = (float*)d_out;

    k_zero<<<1, 256>>>();
    k_tmean<<<dim3((NQ + 255) / 256, Bx), 256>>>(seq, cl);
    k_predfinal<<<(Bx * Nn + 255) / 256, 256>>>(out);
}

// round 8
// speedup vs baseline: 4.9952x; 1.2674x over previous
#include <cuda_runtime.h>

#define Bx 32
#define Tt 36
#define Nn 10000
#define Ff 3
#define Hh 10
#define Rr 20
#define NQ (Nn * Ff / 4)   // 7500 float4 per (b,t) row
#define NCHUNK 30          // 30 blocks of 256 threads cover NQ

// Scratch (no device allocation allowed -> __device__ globals).
// All of these are pure-overwrite per call (no cross-replay accumulation)
// except g_nancnt, which k_final resets after consuming it.
__device__ float g_psum[Bx * NCHUNK * Rr];  // per-(b,chunk) regional sums
__device__ int   g_pcnt[Bx * NCHUNK * Rr];  // per-(b,chunk) regional counts
__device__ int   g_nanlist[Bx * Nn];        // packed b*Nn+n of all-NaN nodes
__device__ int   g_nancnt;                  // list length (reset by k_final)

// ---------------------------------------------------------------------------
// Kernel A (heavy, HBM-bound, fully fused): grid = (NCHUNK, Bx).
// Main loop: 36 coalesced float4 loads per thread (512B per warp-load).
// Epilogue per channel-0 component:
//   - write time_mean straight into out_pred (10 strided stores); NaN values
//     are written as-is and patched by k_final (expected all-NaN nodes: ~0,
//     P = 0.05^36)
//   - bin into per-block shared regional histogram (20 sums + 20 counts)
// Flush: histogram -> this block's private g_psum/g_pcnt slot (overwrite, no
// global atomics -> no zeroing kernel needed across graph replays).
// cluster_id int64-vs-int32 detection per block (int64 LE in [0,20) => odd
// words all zero; false-positive prob for true int32 ~ 20^-64).
// ---------------------------------------------------------------------------
__global__ void k_main(const float4* __restrict__ seq, const int* __restrict__ cl,
                       float* __restrict__ out) {
    __shared__ float s_rsum[Rr];
    __shared__ int   s_rcnt[Rr];
    __shared__ int   s_flag;

    int tid = threadIdx.x;
    int b   = blockIdx.y;
    int j   = blockIdx.x * blockDim.x + tid;   // float4 column in [0, NQ)

    if (tid < Rr) { s_rsum[tid] = 0.f; s_rcnt[tid] = 0; }
    if (tid == 0) s_flag = 1;
    __syncthreads();
    if (tid < 64) {
        bool ok = (cl[2 * tid + 1] == 0) && ((unsigned)cl[2 * tid] < (unsigned)Rr);
        if (!ok) atomicAnd(&s_flag, 0);
    }

    float s0 = 0.f, s1 = 0.f, s2 = 0.f, s3 = 0.f;
    int   c0 = 0,   c1 = 0,   c2 = 0,   c3 = 0;
    if (j < NQ) {
        const float4* p = seq + (size_t)b * Tt * NQ + j;
#pragma unroll 6
        for (int t = 0; t < Tt; t++) {
            float4 v = p[(size_t)t * NQ];
            bool o0 = (v.x == v.x), o1 = (v.y == v.y);
            bool o2 = (v.z == v.z), o3 = (v.w == v.w);
            s0 += o0 ? v.x : 0.f;  c0 += o0;
            s1 += o1 ? v.y : 0.f;  c1 += o1;
            s2 += o2 ? v.z : 0.f;  c2 += o2;
            s3 += o3 ? v.w : 0.f;  c3 += o3;
        }
    }
    __syncthreads();   // s_flag ready
    int is64 = s_flag;

    if (j < NQ) {
        float s[4] = {s0, s1, s2, s3};
        int   c[4] = {c0, c1, c2, c3};
        int f0 = 4 * j;
        float* ob = out + (size_t)b * Hh * Nn;
#pragma unroll
        for (int cc = 0; cc < 4; cc++) {
            int f = f0 + cc;
            if (f % 3 == 0) {                      // channel-0 component
                int   node = f / 3;
                float tm = s[cc] / (float)c[cc];   // 0/0 -> NaN
                float* o = ob + node;
#pragma unroll
                for (int h = 0; h < Hh; h++) o[(size_t)h * Nn] = tm;
                if (tm == tm) {
                    int id = is64 ? cl[2 * node] : cl[node];
                    atomicAdd(&s_rsum[id], tm);
                    atomicAdd(&s_rcnt[id], 1);
                } else {
                    int slot = atomicAdd(&g_nancnt, 1);
                    g_nanlist[slot] = b * Nn + node;
                }
            }
        }
    }
    __syncthreads();

    if (tid < Rr) {
        int slot = (b * NCHUNK + blockIdx.x) * Rr + tid;
        g_psum[slot] = s_rsum[tid];
        g_pcnt[slot] = s_rcnt[tid];
    }
}

// ---------------------------------------------------------------------------
// Kernel B (single block, 640 threads): thread (b,r) reduces its 30 chunk
// partials -> regional sum/count; g1 = sum of all partials / counts;
// g2 = nanmean(regional); writes the 6400 regional outputs (NaN -> g2);
// patches the NaN-list entries in out_pred with g1; resets the list counter.
// ---------------------------------------------------------------------------
__global__ void k_final(float* __restrict__ out) {
    __shared__ double s_ws[20];
    __shared__ int    s_wc[20];
    __shared__ double s_gs[20];
    __shared__ int    s_gc[20];
    __shared__ float  s_regv[Bx * Rr];
    __shared__ float  s_g1, s_g2;

    int tid  = threadIdx.x;     // 0..639
    int lane = tid & 31;
    int wid  = tid >> 5;        // 0..19

    // Per-(b,r) reduction over 30 chunks
    double rs = 0.0; int rc = 0;
    {
        int b = tid / Rr;
        int r = tid - b * Rr;
#pragma unroll 6
        for (int c = 0; c < NCHUNK; c++) {
            int slot = (b * NCHUNK + c) * Rr + r;
            rs += (double)g_psum[slot];
            rc += g_pcnt[slot];
        }
        s_regv[tid] = (float)(rs / (double)rc);   // 0/0 -> NaN
    }

    // g1: total valid-tm sum/count = sum of all (b,r) partials
    double gs = rs; int gc = rc;
#pragma unroll
    for (int o = 16; o; o >>= 1) {
        gs += __shfl_down_sync(0xffffffffu, gs, o);
        gc += __shfl_down_sync(0xffffffffu, gc, o);
    }
    if (lane == 0) { s_gs[wid] = gs; s_gc[wid] = gc; }

    // g2: nanmean over the 640 regional values
    float rv = s_regv[tid];   // own value (just wrote it; pre-sync read of own slot is fine)
    double ls = (rv == rv) ? (double)rv : 0.0;
    int    lc = (rv == rv) ? 1 : 0;
#pragma unroll
    for (int o = 16; o; o >>= 1) {
        ls += __shfl_down_sync(0xffffffffu, ls, o);
        lc += __shfl_down_sync(0xffffffffu, lc, o);
    }
    if (lane == 0) { s_ws[wid] = ls; s_wc[wid] = lc; }
    __syncthreads();
    if (tid == 0) {
        double tg = 0.0; long long tgc = 0;
        double t2 = 0.0; int t2c = 0;
#pragma unroll
        for (int w = 0; w < 20; w++) {
            tg += s_gs[w]; tgc += s_gc[w];
            t2 += s_ws[w]; t2c += s_wc[w];
        }
        s_g1 = (float)(tg / (double)tgc);
        s_g2 = (float)(t2 / (double)t2c);
    }
    __syncthreads();
    float g1 = s_g1, g2 = s_g2;

    // Regional outputs: [B, H, R]
    float* oreg = out + (size_t)Bx * Hh * Nn;
    for (int i = tid; i < Bx * Hh * Rr; i += blockDim.x) {
        int b = i / (Hh * Rr);
        int r = i % Rr;
        float v = s_regv[b * Rr + r];
        oreg[i] = (v == v) ? v : g2;
    }

    // Patch all-NaN nodes in out_pred with g1 (expected ~0 entries)
    int cnt = g_nancnt;
    for (int i = tid; i < cnt; i += blockDim.x) {
        int packed = g_nanlist[i];
        int b = packed / Nn;
        int n = packed - b * Nn;
        float* o = out + (size_t)b * Hh * Nn + n;
#pragma unroll
        for (int h = 0; h < Hh; h++) o[(size_t)h * Nn] = g1;
    }
    __syncthreads();
    if (tid == 0) g_nancnt = 0;   // reset for next graph replay
}

extern "C" void kernel_launch(void* const* d_in, const int* in_sizes, int n_in,
                              void* d_out, int out_size) {
    (void)in_sizes; (void)n_in; (void)out_size;
    const float4* seq = (const float4*)d_in[0];
    const int*    cl  = (const int*)d_in[1];
    float*        out = (float*)d_out;

    k_main<<<dim3(NCHUNK, Bx), 256>>>(seq, cl, out);
    k_final<<<1, Bx * Rr>>>(out);
}

// round 9
// speedup vs baseline: 5.4075x; 1.0825x over previous
#include <cuda_runtime.h>

#define Bx 32
#define Tt 36
#define Nn 10000
#define Ff 3
#define Hh 10
#define Rr 20
#define NQ (Nn * Ff / 4)   // 7500 float4 per (b,t) row
#define NCHUNK 30          // 30 blocks of 256 threads cover NQ
#define NBLOCKS (NCHUNK * Bx)

// Scratch (no device allocation allowed -> __device__ globals).
// Zero-initialized at module load; the last block resets everything to zero
// after consuming it, so every graph replay starts from the same state.
__device__ float g_rsum[Bx * Rr];    // per-(b,r) regional sums   (atomics)
__device__ int   g_rcnt[Bx * Rr];    // per-(b,r) regional counts (atomics)
__device__ int   g_nanlist[4096];    // packed b*Nn+n of all-NaN nodes (exp. 0)
__device__ int   g_nancnt;           // list length
__device__ unsigned g_done;          // finished-block ticket counter

// ---------------------------------------------------------------------------
// Single fused kernel. grid = (NCHUNK, Bx), one block per (b, 256-float4
// chunk).
//  Main loop: 36 coalesced float4 loads per thread (512B per warp-load).
//  Epilogue per channel-0 component:
//    - write time_mean straight into out_pred (10 strided stores; NaNs
//      written as-is, patched by the last block; P(all-NaN node)=0.05^36)
//    - bin into per-block shared regional histogram
//  Flush: 40 global atomicAdds per block into g_rsum/g_rcnt.
//  Last block (threadfence + ticket): reads the 1280 accumulator words,
//  computes regional/g1/g2, writes the 6400 regional outputs, patches the
//  NaN list, and zeroes all scratch for the next replay.
//  cluster_id int64-vs-int32 detection per block (int64 LE in [0,20) => odd
//  words all zero; false-positive prob for true int32 ~ 20^-64).
// ---------------------------------------------------------------------------
__global__ void k_main(const float4* __restrict__ seq, const int* __restrict__ cl,
                       float* __restrict__ out) {
    __shared__ float s_rsum[Rr];
    __shared__ int   s_rcnt[Rr];
    __shared__ int   s_flag;
    __shared__ int   s_last;

    int tid = threadIdx.x;
    int b   = blockIdx.y;
    int j   = blockIdx.x * blockDim.x + tid;   // float4 column in [0, NQ)

    if (tid < Rr) { s_rsum[tid] = 0.f; s_rcnt[tid] = 0; }
    if (tid == 0) s_flag = 1;
    __syncthreads();
    if (tid < 64) {
        bool ok = (cl[2 * tid + 1] == 0) && ((unsigned)cl[2 * tid] < (unsigned)Rr);
        if (!ok) atomicAnd(&s_flag, 0);
    }

    float s0 = 0.f, s1 = 0.f, s2 = 0.f, s3 = 0.f;
    int   c0 = 0,   c1 = 0,   c2 = 0,   c3 = 0;
    if (j < NQ) {
        const float4* p = seq + (size_t)b * Tt * NQ + j;
#pragma unroll 6
        for (int t = 0; t < Tt; t++) {
            float4 v = p[(size_t)t * NQ];
            bool o0 = (v.x == v.x), o1 = (v.y == v.y);
            bool o2 = (v.z == v.z), o3 = (v.w == v.w);
            s0 += o0 ? v.x : 0.f;  c0 += o0;
            s1 += o1 ? v.y : 0.f;  c1 += o1;
            s2 += o2 ? v.z : 0.f;  c2 += o2;
            s3 += o3 ? v.w : 0.f;  c3 += o3;
        }
    }
    __syncthreads();   // s_flag ready
    int is64 = s_flag;

    if (j < NQ) {
        float s[4] = {s0, s1, s2, s3};
        int   c[4] = {c0, c1, c2, c3};
        int f0 = 4 * j;
        float* ob = out + (size_t)b * Hh * Nn;
#pragma unroll
        for (int cc = 0; cc < 4; cc++) {
            int f = f0 + cc;
            if (f % 3 == 0) {                      // channel-0 component
                int   node = f / 3;
                float tm = s[cc] / (float)c[cc];   // 0/0 -> NaN
                float* o = ob + node;
#pragma unroll
                for (int h = 0; h < Hh; h++) o[(size_t)h * Nn] = tm;
                if (tm == tm) {
                    int id = is64 ? cl[2 * node] : cl[node];
                    atomicAdd(&s_rsum[id], tm);
                    atomicAdd(&s_rcnt[id], 1);
                } else {
                    int slot = atomicAdd(&g_nancnt, 1);
                    g_nanlist[slot & 4095] = b * Nn + node;
                }
            }
        }
    }
    __syncthreads();

    // Flush block histogram into global accumulators
    if (tid < Rr) {
        atomicAdd(&g_rsum[b * Rr + tid], s_rsum[tid]);
        atomicAdd(&g_rcnt[b * Rr + tid], s_rcnt[tid]);
    }

    // ---- last-block finalization -------------------------------------------
    __threadfence();
    if (tid == 0) {
        unsigned t = atomicAdd(&g_done, 1u);
        s_last = (t == NBLOCKS - 1);
    }
    __syncthreads();
    if (!s_last) return;

    __shared__ double s_ws[8];
    __shared__ int    s_wc[8];
    __shared__ double s_gs[8];
    __shared__ long long s_gc[8];
    __shared__ float  s_regv[Bx * Rr];
    __shared__ float  s_g1, s_g2;

    int lane = tid & 31;
    int wid  = tid >> 5;

    // regional[b,r] + partials for g1 (total valid sum/count) and g2
    double gs = 0.0; long long gc = 0;
    double ls = 0.0; int lc = 0;
    for (int i = tid; i < Bx * Rr; i += blockDim.x) {
        float rs = g_rsum[i];
        int   rc = g_rcnt[i];
        float v  = rs / (float)rc;   // 0/0 -> NaN
        s_regv[i] = v;
        gs += (double)rs; gc += rc;
        if (v == v) { ls += (double)v; lc++; }
    }
#pragma unroll
    for (int o = 16; o; o >>= 1) {
        gs += __shfl_down_sync(0xffffffffu, gs, o);
        gc += __shfl_down_sync(0xffffffffu, gc, o);
        ls += __shfl_down_sync(0xffffffffu, ls, o);
        lc += __shfl_down_sync(0xffffffffu, lc, o);
    }
    if (lane == 0) { s_gs[wid] = gs; s_gc[wid] = gc; s_ws[wid] = ls; s_wc[wid] = lc; }
    __syncthreads();
    if (tid == 0) {
        double tg = 0.0; long long tgc = 0;
        double t2 = 0.0; int t2c = 0;
#pragma unroll
        for (int w = 0; w < 8; w++) {
            tg += s_gs[w]; tgc += s_gc[w];
            t2 += s_ws[w]; t2c += s_wc[w];
        }
        s_g1 = (float)(tg / (double)tgc);
        s_g2 = (float)(t2 / (double)t2c);
    }
    __syncthreads();
    float g1 = s_g1, g2 = s_g2;

    // Regional outputs: [B, H, R]
    float* oreg = out + (size_t)Bx * Hh * Nn;
    for (int i = tid; i < Bx * Hh * Rr; i += blockDim.x) {
        int bb = i / (Hh * Rr);
        int r  = i % Rr;
        float v = s_regv[bb * Rr + r];
        oreg[i] = (v == v) ? v : g2;
    }

    // Patch all-NaN nodes in out_pred with g1 (expected 0 entries)
    int cnt = g_nancnt;
    if (cnt > 4096) cnt = 4096;
    for (int i = tid; i < cnt; i += blockDim.x) {
        int packed = g_nanlist[i];
        int bb = packed / Nn;
        int n  = packed - bb * Nn;
        float* o = out + (size_t)bb * Hh * Nn + n;
#pragma unroll
        for (int h = 0; h < Hh; h++) o[(size_t)h * Nn] = g1;
    }
    __syncthreads();

    // Reset all scratch for the next graph replay
    for (int i = tid; i < Bx * Rr; i += blockDim.x) { g_rsum[i] = 0.f; g_rcnt[i] = 0; }
    if (tid == 0) { g_nancnt = 0; g_done = 0u; }
}

extern "C" void kernel_launch(void* const* d_in, const int* in_sizes, int n_in,
                              void* d_out, int out_size) {
    (void)in_sizes; (void)n_in; (void)out_size;
    const float4* seq = (const float4*)d_in[0];
    const int*    cl  = (const int*)d_in[1];
    float*        out = (float*)d_out;

    k_main<<<dim3(NCHUNK, Bx), 256>>>(seq, cl, out);
}